// round 11
// baseline (speedup 1.0000x reference)
#include <cuda_runtime.h>

#define BB 4
#define NT 256
#define NZ 384
#define NXX 384
#define NREC 128
#define DTc 0.001f
#define DHc 10.0f

#define NBLK 128
#define BLK_PER_B (NBLK / BB)      // 32 blocks per batch
#define ROWS 12                    // owned rows per block
#define NPAIR (NXX / 2)            // 192 column pairs
#define NGRP 4                     // row groups
#define RPT 3                      // rows per thread
#define NTHR (NPAIR * NGRP)        // 768 threads
#define SROWS (ROWS + 2)           // smem rows: [0]=top ghost, 1..12 owned, [13]=bot ghost

// Packed word: hi32 = exchange-event counter E, lo32 = float bits.
// words per column: [0]=u(t) depth1, [1]=u(t) depth2, [2]=u(t-1) depth1
__device__ unsigned long long d_pack[2][NBLK][2][3][NXX];
#define SLOT_OFF (NBLK * 2 * 3 * NXX)

__global__ void zero_kernel() {
    const int n = 2 * NBLK * 2 * 3 * NXX;
    for (int i = blockIdx.x * blockDim.x + threadIdx.x; i < n;
         i += gridDim.x * blockDim.x)
        ((unsigned long long*)d_pack)[i] = 0ull;
}

__device__ __forceinline__ unsigned long long ld_vol_u64(
        const unsigned long long* p) {
    unsigned long long v;
    asm volatile("ld.volatile.global.u64 %0, [%1];" : "=l"(v) : "l"(p));
    return v;
}
__device__ __forceinline__ void st_vol_u64(unsigned long long* p,
                                           unsigned long long v) {
    asm volatile("st.volatile.global.u64 [%0], %1;" :: "l"(p), "l"(v));
}

__global__ __launch_bounds__(NTHR, 1) void wave_kernel(
    const float* __restrict__ xsrc,   // [B, NT]
    const float* __restrict__ vp,     // [NZ, NX]
    const int*   __restrict__ src_y,
    const int*   __restrict__ src_x,
    const int*   __restrict__ rec_y,
    const int*   __restrict__ rec_x,
    float*       __restrict__ out)    // [NT, B, NREC]
{
    __shared__ float sb0[SROWS * NXX];
    __shared__ float sb1[SROWS * NXX];

    const int tid = threadIdx.x;
    const int p   = tid % NPAIR;
    const int g   = tid / NPAIR;            // warp-uniform (6 warps/group)
    const int x0  = 2 * p;
    const int x1  = x0 + 1;
    const int blk = blockIdx.x;
    const int b   = blk / BLK_PER_B;
    const int bib = blk % BLK_PER_B;
    const int z0  = bib * ROWS;
    const float inv_dh2 = 1.0f / (DHc * DHc);

    const int topBlk = (bib > 0) ? blk - 1 : -1;
    const int botBlk = (bib < BLK_PER_B - 1) ? blk + 1 : -1;
    const bool isTop = (g == 0);
    const bool isBot = (g == NGRP - 1);
    const int  nb    = isTop ? topBlk : (isBot ? botBlk : -1);
    const bool hasNb = (nb >= 0);
    const int  side  = isTop ? 0 : 1;

    const int sy = src_y[b];
    const int sx = src_x[b];

    float ucA[RPT], ucB[RPT], pvA[RPT], pvB[RPT], csA[RPT], csB[RPT];
    unsigned smA = 0, smB = 0;

#pragma unroll
    for (int k = 0; k < RPT; k++) {
        const int zg = z0 + g * RPT + k;
        ucA[k] = 0.0f; ucB[k] = 0.0f;
        pvA[k] = 0.0f; pvB[k] = 0.0f;
        const float cA = vp[zg * NXX + x0] * DTc;
        const float cB = vp[zg * NXX + x1] * DTc;
        const bool zok = (zg > 0 && zg < NZ - 1);
        csA[k] = (zok && x0 > 0)       ? (cA * cA * inv_dh2) : 0.0f;
        csB[k] = (zok && x1 < NXX - 1) ? (cB * cB * inv_dh2) : 0.0f;
        if (zg == sy && x0 == sx) smA |= (1u << k);
        if (zg == sy && x1 == sx) smB |= (1u << k);
        const int pr = (1 + g * RPT + k) * NXX;
        sb0[pr + x0] = 0.0f; sb0[pr + x1] = 0.0f;
        sb1[pr + x0] = 0.0f; sb1[pr + x1] = 0.0f;
    }

    // ghost-row state (boundary groups with a neighbor only)
    float nU1aA = 0.f, nU1aB = 0.f;   // neighbor u(t) depth1
    float nU1bA = 0.f, nU1bB = 0.f;   // neighbor u(t) depth2
    float pvInA = 0.f, pvInB = 0.f;   // neighbor u(t-1) depth1
    float gUA = 0.f, gUB = 0.f;       // my computed ghost u(t)
    float csGA = 0.f, csGB = 0.f;
    bool  srcGA = false, srcGB = false;
    const int gRow = isTop ? 0 : (SROWS - 1) * NXX;
    if (hasNb) {
        const int zg = isTop ? (z0 - 1) : (z0 + ROWS);
        const float cA = vp[zg * NXX + x0] * DTc;
        const float cB = vp[zg * NXX + x1] * DTc;
        csGA = (x0 > 0)       ? (cA * cA * inv_dh2) : 0.0f;
        csGB = (x1 < NXX - 1) ? (cB * cB * inv_dh2) : 0.0f;
        srcGA = (zg == sy && x0 == sx);
        srcGB = (zg == sy && x1 == sx);
        // zero ghost rows of both buffers
        sb0[gRow + x0] = 0.f; sb0[gRow + x1] = 0.f;
        sb1[gRow + x0] = 0.f; sb1[gRow + x1] = 0.f;
    }

    int rmine = 0, roff = 0;
    float* outp = out;
    if (tid < NREC) {
        const int ry = rec_y[tid];
        const int rx = rec_x[tid];
        rmine = (ry >= z0 && ry < z0 + ROWS);
        roff  = (ry - z0 + 1) * NXX + rx;
        outp  = out + b * NREC + tid;
    }
    const float* xs = xsrc + b * NT;

    const int pbase = (1 + g * RPT) * NXX + x0;
    const int dxl   = (x0 > 0) ? 1 : 0;
    const int dxr   = (x1 < NXX - 1) ? 1 : 0;

    unsigned long long* pubA = &d_pack[0][blk][side][0][x0];
    const unsigned long long* polA =
        hasNb ? &d_pack[0][nb][side ^ 1][0][x0] : pubA;

    __syncthreads();

    #define DO_ROW(k, upA_, upB_, dnA_, dnB_, RBUF, WBUF, xt)                   \
    {                                                                           \
        const int pr = pbase + (k) * NXX;                                       \
        const float uA = ucA[k], uB = ucB[k];                                   \
        const float Lv = RBUF[pr - dxl];                                        \
        const float Rv = RBUF[pr + 1 + dxr];                                    \
        const float lapA = (upA_) + (dnA_) + Lv + uB - 4.0f * uA;               \
        const float lapB = (upB_) + (dnB_) + uA + Rv - 4.0f * uB;               \
        float hA = fmaf(csA[k], lapA, 2.0f * uA - pvA[k]);                      \
        float hB = fmaf(csB[k], lapB, 2.0f * uB - pvB[k]);                      \
        if (smA & (1u << (k))) hA += xt;                                        \
        if (smB & (1u << (k))) hB += xt;                                        \
        pvA[k] = uA; pvB[k] = uB;                                               \
        ucA[k] = hA; ucB[k] = hB;                                               \
        *(float2*)&WBUF[pr] = make_float2(hA, hB);                              \
    }

    // EVEN step: no global sync; boundary groups also compute the ghost row.
    #define STEP_E(T, RBUF, WBUF)                                               \
    {                                                                           \
        const int   t  = (T);                                                   \
        const float xt = xs[t];                                                 \
        if (t > 0 && rmine) { outp[(t - 1) * (BB * NREC)] = RBUF[roff]; }       \
        const float a0 = ucA[0], b0 = ucB[0];                                   \
        const float a1 = ucA[1], b1 = ucB[1];                                   \
        const float a2 = ucA[2], b2 = ucB[2];                                   \
        if (hasNb) { /* ghost u(t): center nU1a, prev pvIn */                   \
            const float GL = RBUF[gRow + x0 - dxl];                             \
            const float GR = RBUF[gRow + x1 + dxr];                             \
            const float in0 = isTop ? a0 : a2;                                  \
            const float in1 = isTop ? b0 : b2;                                  \
            const float lgA = nU1bA + in0 + GL + nU1aB - 4.0f * nU1aA;          \
            const float lgB = nU1bB + in1 + nU1aA + GR - 4.0f * nU1aB;          \
            float gA = fmaf(csGA, lgA, 2.0f * nU1aA - pvInA);                   \
            float gB = fmaf(csGB, lgB, 2.0f * nU1aB - pvInB);                   \
            if (srcGA) gA += xt;                                                \
            if (srcGB) gB += xt;                                                \
            gUA = gA; gUB = gB;                                                 \
        }                                                                       \
        if (isTop) {                                                            \
            DO_ROW(0, nU1aA, nU1aB, a1, b1, RBUF, WBUF, xt);                    \
            DO_ROW(1, a0, b0, a2, b2, RBUF, WBUF, xt);                          \
            const float2 dn = *(const float2*)&RBUF[pbase + RPT * NXX];         \
            DO_ROW(2, a1, b1, dn.x, dn.y, RBUF, WBUF, xt);                      \
        } else if (isBot) {                                                     \
            const float2 up = *(const float2*)&RBUF[pbase - NXX];               \
            DO_ROW(0, up.x, up.y, a1, b1, RBUF, WBUF, xt);                      \
            DO_ROW(1, a0, b0, a2, b2, RBUF, WBUF, xt);                          \
            DO_ROW(2, a1, b1, nU1aA, nU1aB, RBUF, WBUF, xt);                    \
        } else {                                                                \
            const float2 up = *(const float2*)&RBUF[pbase - NXX];               \
            DO_ROW(0, up.x, up.y, a1, b1, RBUF, WBUF, xt);                      \
            DO_ROW(1, a0, b0, a2, b2, RBUF, WBUF, xt);                          \
            const float2 dn = *(const float2*)&RBUF[pbase + RPT * NXX];         \
            DO_ROW(2, a1, b1, dn.x, dn.y, RBUF, WBUF, xt);                      \
        }                                                                       \
        __syncthreads();                                                        \
    }

    // ODD step: publish after boundary rows; spec; consume at end; stage ghost.
    #define STEP_O(T, RBUF, WBUF, SOFF)                                         \
    {                                                                           \
        const int   t  = (T);                                                   \
        const int   E  = ((T) + 1) / 2;                                         \
        const float xt = xs[t];                                                 \
        if (rmine) { outp[(t - 1) * (BB * NREC)] = RBUF[roff]; }                \
        const float a0 = ucA[0], b0 = ucB[0];                                   \
        const float a1 = ucA[1], b1 = ucB[1];                                   \
        const float a2 = ucA[2], b2 = ucB[2];                                   \
        unsigned long long s0a = 0, s0b = 0, s1a = 0, s1b = 0,                  \
                           s2a = 0, s2b = 0;                                    \
        if (isTop) {                                                            \
            DO_ROW(0, gUA, gUB, a1, b1, RBUF, WBUF, xt);                        \
            DO_ROW(1, a0, b0, a2, b2, RBUF, WBUF, xt);                          \
            if (hasNb) {                                                        \
                const unsigned long long hi = (unsigned long long)(unsigned)E << 32; \
                st_vol_u64(pubA + (SOFF),             hi | __float_as_uint(ucA[0])); \
                st_vol_u64(pubA + (SOFF) + 1,         hi | __float_as_uint(ucB[0])); \
                st_vol_u64(pubA + (SOFF) + NXX,       hi | __float_as_uint(ucA[1])); \
                st_vol_u64(pubA + (SOFF) + NXX + 1,   hi | __float_as_uint(ucB[1])); \
                st_vol_u64(pubA + (SOFF) + 2*NXX,     hi | __float_as_uint(pvA[0])); \
                st_vol_u64(pubA + (SOFF) + 2*NXX + 1, hi | __float_as_uint(pvB[0])); \
                s0a = ld_vol_u64(polA + (SOFF));                                \
                s0b = ld_vol_u64(polA + (SOFF) + 1);                            \
                s1a = ld_vol_u64(polA + (SOFF) + NXX);                          \
                s1b = ld_vol_u64(polA + (SOFF) + NXX + 1);                      \
                s2a = ld_vol_u64(polA + (SOFF) + 2*NXX);                        \
                s2b = ld_vol_u64(polA + (SOFF) + 2*NXX + 1);                    \
            }                                                                   \
            const float2 dn = *(const float2*)&RBUF[pbase + RPT * NXX];         \
            DO_ROW(2, a1, b1, dn.x, dn.y, RBUF, WBUF, xt);                      \
        } else if (isBot) {                                                     \
            DO_ROW(2, a1, b1, gUA, gUB, RBUF, WBUF, xt);                        \
            DO_ROW(1, a0, b0, a2, b2, RBUF, WBUF, xt);                          \
            if (hasNb) {                                                        \
                const unsigned long long hi = (unsigned long long)(unsigned)E << 32; \
                st_vol_u64(pubA + (SOFF),             hi | __float_as_uint(ucA[2])); \
                st_vol_u64(pubA + (SOFF) + 1,         hi | __float_as_uint(ucB[2])); \
                st_vol_u64(pubA + (SOFF) + NXX,       hi | __float_as_uint(ucA[1])); \
                st_vol_u64(pubA + (SOFF) + NXX + 1,   hi | __float_as_uint(ucB[1])); \
                st_vol_u64(pubA + (SOFF) + 2*NXX,     hi | __float_as_uint(pvA[2])); \
                st_vol_u64(pubA + (SOFF) + 2*NXX + 1, hi | __float_as_uint(pvB[2])); \
                s0a = ld_vol_u64(polA + (SOFF));                                \
                s0b = ld_vol_u64(polA + (SOFF) + 1);                            \
                s1a = ld_vol_u64(polA + (SOFF) + NXX);                          \
                s1b = ld_vol_u64(polA + (SOFF) + NXX + 1);                      \
                s2a = ld_vol_u64(polA + (SOFF) + 2*NXX);                        \
                s2b = ld_vol_u64(polA + (SOFF) + 2*NXX + 1);                    \
            }                                                                   \
            const float2 up = *(const float2*)&RBUF[pbase - NXX];               \
            DO_ROW(0, up.x, up.y, a1, b1, RBUF, WBUF, xt);                      \
        } else {                                                                \
            const float2 up = *(const float2*)&RBUF[pbase - NXX];               \
            DO_ROW(0, up.x, up.y, a1, b1, RBUF, WBUF, xt);                      \
            DO_ROW(1, a0, b0, a2, b2, RBUF, WBUF, xt);                          \
            const float2 dn = *(const float2*)&RBUF[pbase + RPT * NXX];         \
            DO_ROW(2, a1, b1, dn.x, dn.y, RBUF, WBUF, xt);                      \
        }                                                                       \
        if (hasNb && t < NT - 1) {                                              \
            unsigned long long v;                                               \
            v = s0a; while ((int)(v >> 32) < E) v = ld_vol_u64(polA + (SOFF));  \
            nU1aA = __uint_as_float((unsigned)v);                               \
            v = s0b; while ((int)(v >> 32) < E) v = ld_vol_u64(polA + (SOFF) + 1); \
            nU1aB = __uint_as_float((unsigned)v);                               \
            v = s1a; while ((int)(v >> 32) < E) v = ld_vol_u64(polA + (SOFF) + NXX); \
            nU1bA = __uint_as_float((unsigned)v);                               \
            v = s1b; while ((int)(v >> 32) < E) v = ld_vol_u64(polA + (SOFF) + NXX + 1); \
            nU1bB = __uint_as_float((unsigned)v);                               \
            v = s2a; while ((int)(v >> 32) < E) v = ld_vol_u64(polA + (SOFF) + 2*NXX); \
            pvInA = __uint_as_float((unsigned)v);                               \
            v = s2b; while ((int)(v >> 32) < E) v = ld_vol_u64(polA + (SOFF) + 2*NXX + 1); \
            pvInB = __uint_as_float((unsigned)v);                               \
            *(float2*)&WBUF[gRow + x0] = make_float2(nU1aA, nU1aB);             \
        }                                                                       \
        __syncthreads();                                                        \
    }

#pragma unroll 1
    for (int tt = 0; tt < NT; tt += 4) {
        STEP_E(tt,     sb0, sb1)
        STEP_O(tt + 1, sb1, sb0, SLOT_OFF)   // E odd  -> slot 1
        STEP_E(tt + 2, sb0, sb1)
        STEP_O(tt + 3, sb1, sb0, 0)          // E even -> slot 0
    }
    #undef STEP_E
    #undef STEP_O
    #undef DO_ROW

    // final receiver gather for t = NT-1 (last wbuf = sb0)
    if (rmine)
        outp[(NT - 1) * (BB * NREC)] = sb0[roff];
}

extern "C" void kernel_launch(void* const* d_in, const int* in_sizes, int n_in,
                              void* d_out, int out_size)
{
    const float* xsrc  = (const float*)d_in[0];
    const float* vp    = (const float*)d_in[1];
    const int*   src_y = (const int*)d_in[2];
    const int*   src_x = (const int*)d_in[3];
    const int*   rec_y = (const int*)d_in[4];
    const int*   rec_x = (const int*)d_in[5];
    float*       out   = (float*)d_out;

    zero_kernel<<<128, 512>>>();
    wave_kernel<<<NBLK, NTHR>>>(xsrc, vp, src_y, src_x, rec_y, rec_x, out);
}

// round 12
// speedup vs baseline: 1.3896x; 1.3896x over previous
#include <cuda_runtime.h>

#define BB 4
#define NT 256
#define NZ 384
#define NXX 384
#define NREC 128
#define DTc 0.001f
#define DHc 10.0f

#define NBLK 128
#define BLK_PER_B (NBLK / BB)      // 32 blocks per batch
#define ROWS 12                    // owned rows per block
#define NPAIR (NXX / 2)            // 192 column pairs
#define NGRP 4                     // row groups
#define RPT 3                      // rows per thread
#define NTHR (NPAIR * NGRP)        // 768 threads

// Packed halo word: hi32 = step counter (t+1 when u(t) published), lo32 = value.
// Single-word atomicity of the 64-bit access IS the synchronization; WAR on slot
// reuse is protected by the publish->consume data-dependency chain.
__device__ unsigned long long d_pack[2][NBLK][2][NXX];
#define SLOT_OFF (NBLK * 2 * NXX)   // u64 elements between slot 0 and slot 1

__global__ void zero_kernel() {
    const int n = 2 * NBLK * 2 * NXX;
    for (int i = blockIdx.x * blockDim.x + threadIdx.x; i < n;
         i += gridDim.x * blockDim.x)
        ((unsigned long long*)d_pack)[i] = 0ull;
}

__device__ __forceinline__ unsigned long long ld_vol_u64(
        const unsigned long long* p) {
    unsigned long long v;
    asm volatile("ld.volatile.global.u64 %0, [%1];" : "=l"(v) : "l"(p));
    return v;
}
__device__ __forceinline__ void st_vol_u64(unsigned long long* p,
                                           unsigned long long v) {
    asm volatile("st.volatile.global.u64 [%0], %1;" :: "l"(p), "l"(v));
}

__global__ __launch_bounds__(NTHR, 1) void wave_kernel(
    const float* __restrict__ xsrc,   // [B, NT]
    const float* __restrict__ vp,     // [NZ, NX]
    const int*   __restrict__ src_y,
    const int*   __restrict__ src_x,
    const int*   __restrict__ rec_y,
    const int*   __restrict__ rec_x,
    float*       __restrict__ out)    // [NT, B, NREC]
{
    __shared__ float sb0[ROWS * NXX];
    __shared__ float sb1[ROWS * NXX];
    __shared__ float sxs[NT];               // staged source trace for this batch

    const int tid = threadIdx.x;
    const int p   = tid % NPAIR;            // column pair
    const int g   = tid / NPAIR;            // row group (warp-uniform: 6 warps/grp)
    const int x0  = 2 * p;
    const int x1  = x0 + 1;
    const int blk = blockIdx.x;
    const int b   = blk / BLK_PER_B;
    const int bib = blk % BLK_PER_B;
    const int z0  = bib * ROWS;
    const int rowbase = g * RPT;
    const float inv_dh2 = 1.0f / (DHc * DHc);

    const int topBlk = (bib > 0) ? blk - 1 : -1;
    const int botBlk = (bib < BLK_PER_B - 1) ? blk + 1 : -1;
    const bool isTop = (g == 0);
    const bool isBot = (g == NGRP - 1);
    const int  nb    = isTop ? topBlk : (isBot ? botBlk : -1);
    const bool hasNb = (nb >= 0);
    const int  side  = isTop ? 0 : 1;

    const int sy = src_y[b];
    const int sx = src_x[b];

    float ucA[RPT], ucB[RPT], pvA[RPT], pvB[RPT], csA[RPT], csB[RPT];
    unsigned smA = 0, smB = 0;              // source masks per column

    // stage the source trace
    for (int i = tid; i < NT; i += NTHR)
        sxs[i] = xsrc[b * NT + i];

#pragma unroll
    for (int k = 0; k < RPT; k++) {
        const int zg = z0 + rowbase + k;
        ucA[k] = 0.0f; ucB[k] = 0.0f;
        pvA[k] = 0.0f; pvB[k] = 0.0f;
        const float cA = vp[zg * NXX + x0] * DTc;
        const float cB = vp[zg * NXX + x1] * DTc;
        const bool zok = (zg > 0 && zg < NZ - 1);
        csA[k] = (zok && x0 > 0)       ? (cA * cA * inv_dh2) : 0.0f;
        csB[k] = (zok && x1 < NXX - 1) ? (cB * cB * inv_dh2) : 0.0f;
        if (zg == sy && x0 == sx) smA |= (1u << k);
        if (zg == sy && x1 == sx) smB |= (1u << k);
        sb0[(rowbase + k) * NXX + x0] = 0.0f;
        sb0[(rowbase + k) * NXX + x1] = 0.0f;
        sb1[(rowbase + k) * NXX + x0] = 0.0f;
        sb1[(rowbase + k) * NXX + x1] = 0.0f;
    }

    int rmine = 0, roff = 0;
    float* outp = out;
    if (tid < NREC) {
        const int ry = rec_y[tid];
        const int rx = rec_x[tid];
        rmine = (ry >= z0 && ry < z0 + ROWS);
        roff  = (ry - z0) * NXX + rx;
        outp  = out + b * NREC + tid;
    }

    const int pbase = rowbase * NXX + x0;
    const int dxl   = (x0 > 0) ? 1 : 0;            // clamped (csc=0 at edges)
    const int dxr   = (x1 < NXX - 1) ? 1 : 0;

    // handshake base pointers, slot 0 (slot 1 = +SLOT_OFF, folded to imm)
    unsigned long long* pubA = &d_pack[0][blk][side][x0];
    const unsigned long long* polA =
        hasNb ? &d_pack[0][nb][side ^ 1][x0] : pubA;

    float hNbA = 0.0f, hNbB = 0.0f;         // neighbor boundary u(t-1)

    __syncthreads();

    // one row of the pair: up/dn explicit, left/right from smem+regs
    #define DO_ROW(k, upA_, upB_, dnA_, dnB_, RBUF, WBUF, xt)                   \
    {                                                                           \
        const int pr = pbase + (k) * NXX;                                       \
        const float uA = ucA[k], uB = ucB[k];                                   \
        const float Lv = RBUF[pr - dxl];                                        \
        const float Rv = RBUF[pr + 1 + dxr];                                    \
        const float lapA = (upA_) + (dnA_) + Lv + uB - 4.0f * uA;               \
        const float lapB = (upB_) + (dnB_) + uA + Rv - 4.0f * uB;               \
        float hA = fmaf(csA[k], lapA, 2.0f * uA - pvA[k]);                      \
        float hB = fmaf(csB[k], lapB, 2.0f * uB - pvB[k]);                      \
        if (smA & (1u << (k))) hA += xt;                                        \
        if (smB & (1u << (k))) hB += xt;                                        \
        pvA[k] = uA; pvB[k] = uB;                                               \
        ucA[k] = hA; ucB[k] = hB;                                               \
        *(float2*)&WBUF[pr] = make_float2(hA, hB);                              \
    }

    #define STEP(T, RBUF, WBUF, SOFF)                                           \
    {                                                                           \
        const int   t  = (T);                                                   \
        const float xt = sxs[t];                                                \
        /* old values (pre-update) needed as vertical neighbors */              \
        const float a0 = ucA[0], b0 = ucB[0];                                   \
        const float a1 = ucA[1], b1 = ucB[1];                                   \
        const float a2 = ucA[2], b2 = ucB[2];                                   \
        unsigned long long specA = 0ull, specB = 0ull;                          \
        /* Phase 1: boundary row first, publish immediately, spec poll #1 */    \
        if (isTop) {                                                            \
            DO_ROW(0, hNbA, hNbB, a1, b1, RBUF, WBUF, xt);                      \
            if (hasNb) {                                                        \
                const unsigned long long hi =                                   \
                    (unsigned long long)(unsigned)(t + 1) << 32;                \
                st_vol_u64(pubA + (SOFF),     hi | __float_as_uint(ucA[0]));    \
                st_vol_u64(pubA + (SOFF) + 1, hi | __float_as_uint(ucB[0]));    \
                if (t < NT - 1) {                                               \
                    specA = ld_vol_u64(polA + (SOFF));                          \
                    specB = ld_vol_u64(polA + (SOFF) + 1);                      \
                }                                                               \
            }                                                                   \
        } else if (isBot) {                                                     \
            DO_ROW(2, a1, b1, hNbA, hNbB, RBUF, WBUF, xt);                      \
            if (hasNb) {                                                        \
                const unsigned long long hi =                                   \
                    (unsigned long long)(unsigned)(t + 1) << 32;                \
                st_vol_u64(pubA + (SOFF),     hi | __float_as_uint(ucA[2]));    \
                st_vol_u64(pubA + (SOFF) + 1, hi | __float_as_uint(ucB[2]));    \
                if (t < NT - 1) {                                               \
                    specA = ld_vol_u64(polA + (SOFF));                          \
                    specB = ld_vol_u64(polA + (SOFF) + 1);                      \
                }                                                               \
            }                                                                   \
        }                                                                       \
        /* receiver gather for step t-1 (moved OFF the publish path) */         \
        if (t > 0 && rmine) { outp[(t - 1) * (BB * NREC)] = RBUF[roff]; }       \
        /* Phase 2: remaining rows */                                           \
        if (isTop) {                                                            \
            DO_ROW(1, a0, b0, a2, b2, RBUF, WBUF, xt);                          \
            const float2 dn = *(const float2*)&RBUF[pbase + RPT * NXX];         \
            DO_ROW(2, a1, b1, dn.x, dn.y, RBUF, WBUF, xt);                      \
        } else if (isBot) {                                                     \
            const float2 up = *(const float2*)&RBUF[pbase - NXX];               \
            DO_ROW(0, up.x, up.y, a1, b1, RBUF, WBUF, xt);                      \
            DO_ROW(1, a0, b0, a2, b2, RBUF, WBUF, xt);                          \
        } else {                                                                \
            const float2 up = *(const float2*)&RBUF[pbase - NXX];               \
            DO_ROW(0, up.x, up.y, a1, b1, RBUF, WBUF, xt);                      \
            DO_ROW(1, a0, b0, a2, b2, RBUF, WBUF, xt);                          \
            const float2 dn = *(const float2*)&RBUF[pbase + RPT * NXX];         \
            DO_ROW(2, a1, b1, dn.x, dn.y, RBUF, WBUF, xt);                      \
        }                                                                       \
        /* Phase 3: double-spec consume */                                      \
        if (hasNb && t < NT - 1) {                                              \
            /* poll #2 issued unconditionally, in flight before check */        \
            unsigned long long rA = ld_vol_u64(polA + (SOFF));                  \
            unsigned long long rB = ld_vol_u64(polA + (SOFF) + 1);              \
            unsigned long long vA = specA, vB = specB;                          \
            if ((int)(vA >> 32) < t + 1) vA = rA;                               \
            if ((int)(vB >> 32) < t + 1) vB = rB;                               \
            while ((int)(vA >> 32) < t + 1) vA = ld_vol_u64(polA + (SOFF));     \
            while ((int)(vB >> 32) < t + 1) vB = ld_vol_u64(polA + (SOFF) + 1); \
            hNbA = __uint_as_float((unsigned)vA);                               \
            hNbB = __uint_as_float((unsigned)vB);                               \
        }                                                                       \
        __syncthreads();                                                        \
    }

#pragma unroll 1
    for (int tt = 0; tt < NT; tt += 2) {
        STEP(tt,     sb0, sb1, 0)          // even t: slot 0
        STEP(tt + 1, sb1, sb0, SLOT_OFF)   // odd  t: slot 1
    }
    #undef STEP
    #undef DO_ROW

    // final receiver gather for t = NT-1 (last wbuf = sb0 since NT even)
    if (rmine)
        outp[(NT - 1) * (BB * NREC)] = sb0[roff];
}

extern "C" void kernel_launch(void* const* d_in, const int* in_sizes, int n_in,
                              void* d_out, int out_size)
{
    const float* xsrc  = (const float*)d_in[0];
    const float* vp    = (const float*)d_in[1];
    const int*   src_y = (const int*)d_in[2];
    const int*   src_x = (const int*)d_in[3];
    const int*   rec_y = (const int*)d_in[4];
    const int*   rec_x = (const int*)d_in[5];
    float*       out   = (float*)d_out;

    zero_kernel<<<128, 512>>>();
    wave_kernel<<<NBLK, NTHR>>>(xsrc, vp, src_y, src_x, rec_y, rec_x, out);
}

// round 13
// speedup vs baseline: 2.3089x; 1.6616x over previous
#include <cuda_runtime.h>

#define BB 4
#define NT 256
#define NZ 384
#define NXX 384
#define NREC 128
#define DTc 0.001f
#define DHc 10.0f

#define NBLK 128
#define BLK_PER_B (NBLK / BB)      // 32 blocks per batch
#define ROWS 12                    // owned rows per block
#define NPAIR (NXX / 2)            // 192 column pairs
#define NGRP 4                     // row groups
#define RPT 3                      // rows per thread
#define NTHR (NPAIR * NGRP)        // 768 threads

// Packed halo word: hi32 = step counter (t+1 when u(t) published), lo32 = value.
// Single-word atomicity of each 64-bit half IS the synchronization; WAR on slot
// reuse is protected by the publish->consume data-dependency chain.
__device__ __align__(16) unsigned long long d_pack[2][NBLK][2][NXX];
#define SLOT_OFF (NBLK * 2 * NXX)   // u64 elements between slot 0 and slot 1

__global__ void zero_kernel() {
    const int n = 2 * NBLK * 2 * NXX;
    for (int i = blockIdx.x * blockDim.x + threadIdx.x; i < n;
         i += gridDim.x * blockDim.x)
        ((unsigned long long*)d_pack)[i] = 0ull;
}

__device__ __forceinline__ unsigned long long ld_vol_u64(
        const unsigned long long* p) {
    unsigned long long v;
    asm volatile("ld.volatile.global.u64 %0, [%1];" : "=l"(v) : "l"(p));
    return v;
}
__device__ __forceinline__ void st_vol_u64x2(unsigned long long* p,
                                             unsigned long long a,
                                             unsigned long long b) {
    asm volatile("st.volatile.global.v2.u64 [%0], {%1, %2};"
                 :: "l"(p), "l"(a), "l"(b));
}
__device__ __forceinline__ void ld_vol_u64x2(const unsigned long long* p,
                                             unsigned long long& a,
                                             unsigned long long& b) {
    asm volatile("ld.volatile.global.v2.u64 {%0, %1}, [%2];"
                 : "=l"(a), "=l"(b) : "l"(p));
}

__global__ __launch_bounds__(NTHR, 1) void wave_kernel(
    const float* __restrict__ xsrc,   // [B, NT]
    const float* __restrict__ vp,     // [NZ, NX]
    const int*   __restrict__ src_y,
    const int*   __restrict__ src_x,
    const int*   __restrict__ rec_y,
    const int*   __restrict__ rec_x,
    float*       __restrict__ out)    // [NT, B, NREC]
{
    __shared__ float sb0[ROWS * NXX];
    __shared__ float sb1[ROWS * NXX];
    __shared__ float sxs[NT];               // staged source trace for this batch

    const int tid = threadIdx.x;
    const int p   = tid % NPAIR;            // column pair
    const int g   = tid / NPAIR;            // row group (warp-uniform: 6 warps/grp)
    const int x0  = 2 * p;
    const int x1  = x0 + 1;
    const int blk = blockIdx.x;
    const int b   = blk / BLK_PER_B;
    const int bib = blk % BLK_PER_B;
    const int z0  = bib * ROWS;
    const int rowbase = g * RPT;
    const float inv_dh2 = 1.0f / (DHc * DHc);

    const int topBlk = (bib > 0) ? blk - 1 : -1;
    const int botBlk = (bib < BLK_PER_B - 1) ? blk + 1 : -1;
    const bool isTop = (g == 0);
    const bool isBot = (g == NGRP - 1);
    const int  nb    = isTop ? topBlk : (isBot ? botBlk : -1);
    const bool hasNb = (nb >= 0);
    const int  side  = isTop ? 0 : 1;

    const int sy = src_y[b];
    const int sx = src_x[b];

    float ucA[RPT], ucB[RPT], pvA[RPT], pvB[RPT], csA[RPT], csB[RPT];
    unsigned smA = 0, smB = 0;              // source masks per column

    // stage the source trace
    for (int i = tid; i < NT; i += NTHR)
        sxs[i] = xsrc[b * NT + i];

#pragma unroll
    for (int k = 0; k < RPT; k++) {
        const int zg = z0 + rowbase + k;
        ucA[k] = 0.0f; ucB[k] = 0.0f;
        pvA[k] = 0.0f; pvB[k] = 0.0f;
        const float cA = vp[zg * NXX + x0] * DTc;
        const float cB = vp[zg * NXX + x1] * DTc;
        const bool zok = (zg > 0 && zg < NZ - 1);
        csA[k] = (zok && x0 > 0)       ? (cA * cA * inv_dh2) : 0.0f;
        csB[k] = (zok && x1 < NXX - 1) ? (cB * cB * inv_dh2) : 0.0f;
        if (zg == sy && x0 == sx) smA |= (1u << k);
        if (zg == sy && x1 == sx) smB |= (1u << k);
        sb0[(rowbase + k) * NXX + x0] = 0.0f;
        sb0[(rowbase + k) * NXX + x1] = 0.0f;
        sb1[(rowbase + k) * NXX + x0] = 0.0f;
        sb1[(rowbase + k) * NXX + x1] = 0.0f;
    }

    int rmine = 0, roff = 0;
    float* outp = out;
    if (tid < NREC) {
        const int ry = rec_y[tid];
        const int rx = rec_x[tid];
        rmine = (ry >= z0 && ry < z0 + ROWS);
        roff  = (ry - z0) * NXX + rx;
        outp  = out + b * NREC + tid;
    }

    const int pbase = rowbase * NXX + x0;
    const int dxl   = (x0 > 0) ? 1 : 0;            // clamped (csc=0 at edges)
    const int dxr   = (x1 < NXX - 1) ? 1 : 0;

    // handshake base pointers, slot 0 (slot 1 = +SLOT_OFF, folded to imm)
    unsigned long long* pubA = &d_pack[0][blk][side][x0];
    const unsigned long long* polA =
        hasNb ? &d_pack[0][nb][side ^ 1][x0] : pubA;

    float hNbA = 0.0f, hNbB = 0.0f;         // neighbor boundary u(t-1)
    unsigned long long specA = 0ull, specB = 0ull;   // in-flight poll results

    __syncthreads();

    // one row of the pair: up/dn explicit, left/right from smem+regs
    #define DO_ROW(k, upA_, upB_, dnA_, dnB_, RBUF, WBUF, xt)                   \
    {                                                                           \
        const int pr = pbase + (k) * NXX;                                       \
        const float uA = ucA[k], uB = ucB[k];                                   \
        const float Lv = RBUF[pr - dxl];                                        \
        const float Rv = RBUF[pr + 1 + dxr];                                    \
        const float lapA = (upA_) + (dnA_) + Lv + uB - 4.0f * uA;               \
        const float lapB = (upB_) + (dnB_) + uA + Rv - 4.0f * uB;               \
        float hA = fmaf(csA[k], lapA, 2.0f * uA - pvA[k]);                      \
        float hB = fmaf(csB[k], lapB, 2.0f * uB - pvB[k]);                      \
        if (smA & (1u << (k))) hA += xt;                                        \
        if (smB & (1u << (k))) hB += xt;                                        \
        pvA[k] = uA; pvB[k] = uB;                                               \
        ucA[k] = hA; ucB[k] = hB;                                               \
        *(float2*)&WBUF[pr] = make_float2(hA, hB);                              \
    }

    // SOFF = slot t&1 (publish / end-of-step poll); PSOFF = slot (t-1)&1
    // (consume previous step's spec).
    #define STEP(T, RBUF, WBUF, SOFF, PSOFF)                                    \
    {                                                                           \
        const int   t  = (T);                                                   \
        const float xt = sxs[t];                                                \
        /* old values (pre-update) needed as vertical neighbors */              \
        const float a0 = ucA[0], b0 = ucB[0];                                   \
        const float a1 = ucA[1], b1 = ucB[1];                                   \
        const float a2 = ucA[2], b2 = ucB[2];                                   \
        /* Phase 0: consume last step's spec = neighbor u(t-1).                 \
           Poll was issued late last step -> counter current; flight time       \
           hidden under the barrier. Retry loop is a safety net. */             \
        if (hasNb && t > 0) {                                                   \
            unsigned long long vA = specA, vB = specB;                          \
            while ((int)(vA >> 32) < t) vA = ld_vol_u64(polA + (PSOFF));        \
            while ((int)(vB >> 32) < t) vB = ld_vol_u64(polA + (PSOFF) + 1);    \
            hNbA = __uint_as_float((unsigned)vA);                               \
            hNbB = __uint_as_float((unsigned)vB);                               \
        }                                                                       \
        /* Phase 1: boundary row first, publish immediately (one STG.128) */    \
        if (isTop) {                                                            \
            DO_ROW(0, hNbA, hNbB, a1, b1, RBUF, WBUF, xt);                      \
            if (hasNb) {                                                        \
                const unsigned long long hi =                                   \
                    (unsigned long long)(unsigned)(t + 1) << 32;                \
                st_vol_u64x2(pubA + (SOFF), hi | __float_as_uint(ucA[0]),       \
                                            hi | __float_as_uint(ucB[0]));      \
            }                                                                   \
        } else if (isBot) {                                                     \
            DO_ROW(2, a1, b1, hNbA, hNbB, RBUF, WBUF, xt);                      \
            if (hasNb) {                                                        \
                const unsigned long long hi =                                   \
                    (unsigned long long)(unsigned)(t + 1) << 32;                \
                st_vol_u64x2(pubA + (SOFF), hi | __float_as_uint(ucA[2]),       \
                                            hi | __float_as_uint(ucB[2]));      \
            }                                                                   \
        }                                                                       \
        /* receiver gather for step t-1 (off the publish path) */               \
        if (t > 0 && rmine) { outp[(t - 1) * (BB * NREC)] = RBUF[roff]; }       \
        /* Phase 2: remaining rows */                                           \
        if (isTop) {                                                            \
            DO_ROW(1, a0, b0, a2, b2, RBUF, WBUF, xt);                          \
            const float2 dn = *(const float2*)&RBUF[pbase + RPT * NXX];         \
            DO_ROW(2, a1, b1, dn.x, dn.y, RBUF, WBUF, xt);                      \
        } else if (isBot) {                                                     \
            const float2 up = *(const float2*)&RBUF[pbase - NXX];               \
            DO_ROW(0, up.x, up.y, a1, b1, RBUF, WBUF, xt);                      \
            DO_ROW(1, a0, b0, a2, b2, RBUF, WBUF, xt);                          \
        } else {                                                                \
            const float2 up = *(const float2*)&RBUF[pbase - NXX];               \
            DO_ROW(0, up.x, up.y, a1, b1, RBUF, WBUF, xt);                      \
            DO_ROW(1, a0, b0, a2, b2, RBUF, WBUF, xt);                          \
            const float2 dn = *(const float2*)&RBUF[pbase + RPT * NXX];         \
            DO_ROW(2, a1, b1, dn.x, dn.y, RBUF, WBUF, xt);                      \
        }                                                                       \
        /* Phase 3: late poll for neighbor u(t); consumed NEXT step */          \
        if (hasNb && t < NT - 1)                                                \
            ld_vol_u64x2(polA + (SOFF), specA, specB);                          \
        __syncthreads();                                                        \
    }

#pragma unroll 1
    for (int tt = 0; tt < NT; tt += 2) {
        STEP(tt,     sb0, sb1, 0, SLOT_OFF)   // even t: publish slot 0
        STEP(tt + 1, sb1, sb0, SLOT_OFF, 0)   // odd  t: publish slot 1
    }
    #undef STEP
    #undef DO_ROW

    // final receiver gather for t = NT-1 (last wbuf = sb0 since NT even)
    if (rmine)
        outp[(NT - 1) * (BB * NREC)] = sb0[roff];
}

extern "C" void kernel_launch(void* const* d_in, const int* in_sizes, int n_in,
                              void* d_out, int out_size)
{
    const float* xsrc  = (const float*)d_in[0];
    const float* vp    = (const float*)d_in[1];
    const int*   src_y = (const int*)d_in[2];
    const int*   src_x = (const int*)d_in[3];
    const int*   rec_y = (const int*)d_in[4];
    const int*   rec_x = (const int*)d_in[5];
    float*       out   = (float*)d_out;

    zero_kernel<<<128, 512>>>();
    wave_kernel<<<NBLK, NTHR>>>(xsrc, vp, src_y, src_x, rec_y, rec_x, out);
}